// round 5
// baseline (speedup 1.0000x reference)
#include <cuda_runtime.h>
#include <cuda_fp16.h>
#include <stdint.h>

// Problem constants: N=100000 nodes, D=128, E=1600000 edges.
#define MAX_N 100000
#define MAX_E 1600000
#define DIM   128

// Device-global scratch (no allocation allowed).
__device__ float2 g_sd2[MAX_N];           // {h.w_dst + b, d[i]}
__device__ float2 g_ss2[MAX_N];           // {h.w_src,     d[i]}
__device__ int    g_counts[MAX_N];        // per-dst degree
__device__ int    g_offsets[MAX_N];       // exclusive scan of counts
__device__ int    g_cursor[MAX_N];        // scatter cursors
__device__ float2 g_es[MAX_E];            // dst-sorted edges: {bitcast(src), coef}
__device__ __half g_hh[(size_t)MAX_N * DIM]; // fp16 replica of h (gather path)

// ---------------------------------------------------------------------------
// 1. Per-node gate scores + fp16 conversion of h. One warp per node.
// ---------------------------------------------------------------------------
__global__ void node_scores_kernel(const float* __restrict__ h,
                                   const float* __restrict__ d,
                                   const float* __restrict__ gate_w,
                                   const float* __restrict__ gate_b,
                                   int n)
{
    int lane = threadIdx.x & 31;
    int row = blockIdx.x * (blockDim.x >> 5) + (threadIdx.x >> 5);
    if (row >= n) return;

    const float4 hv = reinterpret_cast<const float4*>(h)[(size_t)row * (DIM / 4) + lane];
    const float4 wd = reinterpret_cast<const float4*>(gate_w)[lane];
    const float4 ws = reinterpret_cast<const float4*>(gate_w)[32 + lane];

    // fp16 replica (coalesced 8B per lane).
    __half2 p01 = __floats2half2_rn(hv.x, hv.y);
    __half2 p23 = __floats2half2_rn(hv.z, hv.w);
    uint2 packed;
    packed.x = *reinterpret_cast<uint32_t*>(&p01);
    packed.y = *reinterpret_cast<uint32_t*>(&p23);
    reinterpret_cast<uint2*>(g_hh)[(size_t)row * 32 + lane] = packed;

    float sd = hv.x * wd.x + hv.y * wd.y + hv.z * wd.z + hv.w * wd.w;
    float ss = hv.x * ws.x + hv.y * ws.y + hv.z * ws.z + hv.w * ws.w;

    #pragma unroll
    for (int off = 16; off > 0; off >>= 1) {
        sd += __shfl_xor_sync(0xFFFFFFFFu, sd, off);
        ss += __shfl_xor_sync(0xFFFFFFFFu, ss, off);
    }

    if (lane == 0) {
        float di = __ldg(&d[row]);
        g_sd2[row] = make_float2(sd + gate_b[0], di);
        g_ss2[row] = make_float2(ss, di);
    }
}

// ---------------------------------------------------------------------------
// 2. Histogram of dst (counts zeroed by cudaMemsetAsync).
// ---------------------------------------------------------------------------
__global__ void hist_kernel(const int* __restrict__ dst, int num_edges, int n)
{
    int e = blockIdx.x * blockDim.x + threadIdx.x;
    if (e >= num_edges) return;
    int t = __ldg(&dst[e]);
    t = min(max(t, 0), n - 1);
    atomicAdd(&g_counts[t], 1);
}

// ---------------------------------------------------------------------------
// 3. Fused exclusive scan (single block, 1024 threads).
//    Each thread serially scans a contiguous chunk of ~98 counters.
// ---------------------------------------------------------------------------
__global__ void scan_all_kernel(int n)
{
    __shared__ int tsum[1024];
    const int tid = threadIdx.x;
    const int per = (n + 1023) / 1024;
    const int begin = tid * per;
    const int end = min(begin + per, n);

    int sum = 0;
    for (int i = begin; i < end; i++) sum += g_counts[i];
    tsum[tid] = sum;
    __syncthreads();

    // Hillis-Steele inclusive scan over thread totals.
    for (int off = 1; off < 1024; off <<= 1) {
        int v = tsum[tid];
        int add = (tid >= off) ? tsum[tid - off] : 0;
        __syncthreads();
        tsum[tid] = v + add;
        __syncthreads();
    }

    int run = tsum[tid] - sum;   // exclusive base for this chunk
    for (int i = begin; i < end; i++) {
        int c = g_counts[i];
        g_offsets[i] = run;
        g_cursor[i]  = run;
        run += c;
    }
}

// ---------------------------------------------------------------------------
// 4. Scatter edges into dst-sorted order with fully-computed coefficient.
// ---------------------------------------------------------------------------
__global__ void scatter_kernel(const float* __restrict__ w,
                               const int* __restrict__ src,
                               const int* __restrict__ dst,
                               int num_edges, int n)
{
    int e = blockIdx.x * blockDim.x + threadIdx.x;
    if (e >= num_edges) return;
    int s = __ldg(&src[e]);
    int t = __ldg(&dst[e]);
    s = min(max(s, 0), n - 1);
    t = min(max(t, 0), n - 1);

    float2 a = g_sd2[t];   // {sdst+b, d[t]}
    float2 b = g_ss2[s];   // {ssrc,   d[s]}
    float coef = tanhf(a.x + b.x) * a.y * b.y * __ldg(&w[e]);

    int pos = atomicAdd(&g_cursor[t], 1);
    g_es[pos] = make_float2(__int_as_float(s), coef);
}

// ---------------------------------------------------------------------------
// 5. Gather-accumulate from fp16 h replica. One warp per dst node.
//    All lanes broadcast-load the same edge record (1 transaction, L1-hot),
//    4-wide unroll -> 4 independent h-row loads in flight per warp.
// ---------------------------------------------------------------------------
__global__ void gather_kernel(float* __restrict__ z, int n)
{
    int lane = threadIdx.x & 31;
    int t = blockIdx.x * (blockDim.x >> 5) + (threadIdx.x >> 5);
    if (t >= n) return;

    const int start = g_offsets[t];
    const int deg   = g_counts[t];
    const float2* __restrict__ es = g_es + start;
    const uint2* __restrict__ h2 = reinterpret_cast<const uint2*>(g_hh);

    float4 acc = make_float4(0.f, 0.f, 0.f, 0.f);

    int k = 0;
    for (; k + 4 <= deg; k += 4) {
        float2 m0 = __ldg(es + k + 0);
        float2 m1 = __ldg(es + k + 1);
        float2 m2 = __ldg(es + k + 2);
        float2 m3 = __ldg(es + k + 3);
        uint2 a0 = __ldg(&h2[(size_t)__float_as_int(m0.x) * 32 + lane]);
        uint2 a1 = __ldg(&h2[(size_t)__float_as_int(m1.x) * 32 + lane]);
        uint2 a2 = __ldg(&h2[(size_t)__float_as_int(m2.x) * 32 + lane]);
        uint2 a3 = __ldg(&h2[(size_t)__float_as_int(m3.x) * 32 + lane]);

        float2 f;
        f = __half22float2(*reinterpret_cast<__half2*>(&a0.x));
        acc.x += m0.y * f.x; acc.y += m0.y * f.y;
        f = __half22float2(*reinterpret_cast<__half2*>(&a0.y));
        acc.z += m0.y * f.x; acc.w += m0.y * f.y;

        f = __half22float2(*reinterpret_cast<__half2*>(&a1.x));
        acc.x += m1.y * f.x; acc.y += m1.y * f.y;
        f = __half22float2(*reinterpret_cast<__half2*>(&a1.y));
        acc.z += m1.y * f.x; acc.w += m1.y * f.y;

        f = __half22float2(*reinterpret_cast<__half2*>(&a2.x));
        acc.x += m2.y * f.x; acc.y += m2.y * f.y;
        f = __half22float2(*reinterpret_cast<__half2*>(&a2.y));
        acc.z += m2.y * f.x; acc.w += m2.y * f.y;

        f = __half22float2(*reinterpret_cast<__half2*>(&a3.x));
        acc.x += m3.y * f.x; acc.y += m3.y * f.y;
        f = __half22float2(*reinterpret_cast<__half2*>(&a3.y));
        acc.z += m3.y * f.x; acc.w += m3.y * f.y;
    }
    for (; k < deg; k++) {
        float2 m = __ldg(es + k);
        uint2 a = __ldg(&h2[(size_t)__float_as_int(m.x) * 32 + lane]);
        float2 f01 = __half22float2(*reinterpret_cast<__half2*>(&a.x));
        float2 f23 = __half22float2(*reinterpret_cast<__half2*>(&a.y));
        acc.x += m.y * f01.x;
        acc.y += m.y * f01.y;
        acc.z += m.y * f23.x;
        acc.w += m.y * f23.y;
    }

    reinterpret_cast<float4*>(z)[(size_t)t * (DIM / 4) + lane] = acc;
}

// ---------------------------------------------------------------------------
// Launch. Inputs: h[N*D] f32, d[N] f32, w[E] f32, gate_w[2D] f32,
// gate_b[1] f32, src[E] i32, dst[E] i32. Output z[N*D] f32.
// ---------------------------------------------------------------------------
extern "C" void kernel_launch(void* const* d_in, const int* in_sizes, int n_in,
                              void* d_out, int out_size)
{
    const float* h      = (const float*)d_in[0];
    const float* d      = (const float*)d_in[1];
    const float* w      = (const float*)d_in[2];
    const float* gate_w = (const float*)d_in[3];
    const float* gate_b = (const float*)d_in[4];
    const int*   src    = (const int*)d_in[5];
    const int*   dst    = (const int*)d_in[6];
    float*       z      = (float*)d_out;

    const int n = in_sizes[1];      // N
    const int E = in_sizes[2];      // E

    // Zero degree counters via memset (graph-capturable, no alloc).
    void* counts_ptr = nullptr;
    cudaGetSymbolAddress(&counts_ptr, g_counts);
    cudaMemsetAsync(counts_ptr, 0, (size_t)n * sizeof(int));

    // 1. Gate scores + fp16 h conversion (one warp per node).
    node_scores_kernel<<<(n + 7) / 8, 256>>>(h, d, gate_w, gate_b, n);

    // 2. Degree histogram.
    hist_kernel<<<(E + 255) / 256, 256>>>(dst, E, n);

    // 3. Fused exclusive scan + cursor init (single block).
    scan_all_kernel<<<1, 1024>>>(n);

    // 4. Scatter edges into dst-sorted (src, coef) pairs.
    scatter_kernel<<<(E + 255) / 256, 256>>>(w, src, dst, E, n);

    // 5. Register-accumulated segment sum; writes every z row once.
    gather_kernel<<<(n + 7) / 8, 256>>>(z, n);
}

// round 6
// speedup vs baseline: 2.1568x; 2.1568x over previous
#include <cuda_runtime.h>
#include <cuda_fp16.h>
#include <stdint.h>

// Problem constants: N=100000 nodes, D=128, E=1600000 edges.
#define MAX_N 100000
#define MAX_E 1600000
#define DIM   128
#define SCAN_TILE 1024
#define MAX_TILES ((MAX_N + SCAN_TILE - 1) / SCAN_TILE)   // 98

// Device-global scratch (no allocation allowed).
__device__ float2 g_sd2[MAX_N];           // {h.w_dst + b, d[i]}
__device__ float2 g_ss2[MAX_N];           // {h.w_src,     d[i]}
__device__ int    g_counts[MAX_N];        // per-dst degree
__device__ int    g_offsets[MAX_N];       // exclusive scan of counts
__device__ int    g_cursor[MAX_N];        // scatter cursors
__device__ int    g_tilesums[MAX_TILES];  // scan tile totals
__device__ float2 g_es[MAX_E];            // dst-sorted edges: {bitcast(src), coef}
__device__ __half g_hh[(size_t)MAX_N * DIM]; // fp16 replica of h (gather path)

// ---------------------------------------------------------------------------
// 1. Per-node gate scores + fp16 conversion of h. One warp per node.
// ---------------------------------------------------------------------------
__global__ void node_scores_kernel(const float* __restrict__ h,
                                   const float* __restrict__ d,
                                   const float* __restrict__ gate_w,
                                   const float* __restrict__ gate_b,
                                   int n)
{
    int lane = threadIdx.x & 31;
    int row = blockIdx.x * (blockDim.x >> 5) + (threadIdx.x >> 5);
    if (row >= n) return;

    const float4 hv = reinterpret_cast<const float4*>(h)[(size_t)row * (DIM / 4) + lane];
    const float4 wd = reinterpret_cast<const float4*>(gate_w)[lane];
    const float4 ws = reinterpret_cast<const float4*>(gate_w)[32 + lane];

    // fp16 replica (coalesced 8B per lane).
    __half2 p01 = __floats2half2_rn(hv.x, hv.y);
    __half2 p23 = __floats2half2_rn(hv.z, hv.w);
    uint2 packed;
    packed.x = *reinterpret_cast<uint32_t*>(&p01);
    packed.y = *reinterpret_cast<uint32_t*>(&p23);
    reinterpret_cast<uint2*>(g_hh)[(size_t)row * 32 + lane] = packed;

    float sd = hv.x * wd.x + hv.y * wd.y + hv.z * wd.z + hv.w * wd.w;
    float ss = hv.x * ws.x + hv.y * ws.y + hv.z * ws.z + hv.w * ws.w;

    #pragma unroll
    for (int off = 16; off > 0; off >>= 1) {
        sd += __shfl_xor_sync(0xFFFFFFFFu, sd, off);
        ss += __shfl_xor_sync(0xFFFFFFFFu, ss, off);
    }

    if (lane == 0) {
        float di = __ldg(&d[row]);
        g_sd2[row] = make_float2(sd + gate_b[0], di);
        g_ss2[row] = make_float2(ss, di);
    }
}

// ---------------------------------------------------------------------------
// 2. Histogram of dst (counts zeroed by cudaMemsetAsync).
// ---------------------------------------------------------------------------
__global__ void hist_kernel(const int* __restrict__ dst, int num_edges, int n)
{
    int e = blockIdx.x * blockDim.x + threadIdx.x;
    if (e >= num_edges) return;
    int t = __ldg(&dst[e]);
    t = min(max(t, 0), n - 1);
    atomicAdd(&g_counts[t], 1);
}

// ---------------------------------------------------------------------------
// 3a. Per-tile exclusive scan (tile = 1024, coalesced).
// ---------------------------------------------------------------------------
__global__ void scan_tile_kernel(int n)
{
    __shared__ int buf[SCAN_TILE];
    int tid = threadIdx.x;
    int i = blockIdx.x * SCAN_TILE + tid;
    int v = (i < n) ? g_counts[i] : 0;
    buf[tid] = v;
    __syncthreads();
    for (int off = 1; off < SCAN_TILE; off <<= 1) {
        int t = buf[tid];
        if (tid >= off) t += buf[tid - off];
        __syncthreads();
        buf[tid] = t;
        __syncthreads();
    }
    int incl = buf[tid];
    if (i < n) g_offsets[i] = incl - v;      // exclusive, pre-base
    if (tid == SCAN_TILE - 1) g_tilesums[blockIdx.x] = incl;
}

// ---------------------------------------------------------------------------
// 3b. Fused tile-base apply + cursor init. Each block loads all tile sums
//     into smem, thread 0 prefix-scans them (98 ints, trivial), then all
//     threads add the base for their element. Replaces two kernels.
// ---------------------------------------------------------------------------
__global__ void add_base_kernel(int n, int ntiles)
{
    __shared__ int base[MAX_TILES + 1];
    int tid = threadIdx.x;
    if (tid < ntiles) base[tid] = g_tilesums[tid];
    __syncthreads();
    if (tid == 0) {
        int run = 0;
        for (int j = 0; j < ntiles; j++) {
            int c = base[j];
            base[j] = run;      // exclusive
            run += c;
        }
    }
    __syncthreads();

    int i = blockIdx.x * blockDim.x + tid;
    if (i >= n) return;
    int off = g_offsets[i] + base[i / SCAN_TILE];
    g_offsets[i] = off;
    g_cursor[i]  = off;
}

// ---------------------------------------------------------------------------
// 4. Scatter edges into dst-sorted order with fully-computed coefficient.
// ---------------------------------------------------------------------------
__global__ void scatter_kernel(const float* __restrict__ w,
                               const int* __restrict__ src,
                               const int* __restrict__ dst,
                               int num_edges, int n)
{
    int e = blockIdx.x * blockDim.x + threadIdx.x;
    if (e >= num_edges) return;
    int s = __ldg(&src[e]);
    int t = __ldg(&dst[e]);
    s = min(max(s, 0), n - 1);
    t = min(max(t, 0), n - 1);

    float2 a = g_sd2[t];   // {sdst+b, d[t]}
    float2 b = g_ss2[s];   // {ssrc,   d[s]}
    float coef = tanhf(a.x + b.x) * a.y * b.y * __ldg(&w[e]);

    int pos = atomicAdd(&g_cursor[t], 1);
    g_es[pos] = make_float2(__int_as_float(s), coef);
}

// ---------------------------------------------------------------------------
// 5. Gather-accumulate from fp16 h replica. One warp per dst node.
//    Coalesced 32-wide metadata load + shfl broadcast (proven R4 pattern).
// ---------------------------------------------------------------------------
__global__ void gather_kernel(float* __restrict__ z, int n)
{
    int lane = threadIdx.x & 31;
    int t = blockIdx.x * (blockDim.x >> 5) + (threadIdx.x >> 5);
    if (t >= n) return;

    const int start = g_offsets[t];
    const int deg   = g_counts[t];
    const uint2* __restrict__ h2 = reinterpret_cast<const uint2*>(g_hh);

    float4 acc = make_float4(0.f, 0.f, 0.f, 0.f);

    for (int base = 0; base < deg; base += 32) {
        int j = base + lane;
        float2 m = (j < deg) ? g_es[start + j] : make_float2(0.f, 0.f);
        int   sj = __float_as_int(m.x);
        float cj = m.y;
        int cnt = min(32, deg - base);
        #pragma unroll 4
        for (int k = 0; k < cnt; k++) {
            int   s = __shfl_sync(0xFFFFFFFFu, sj, k);
            float c = __shfl_sync(0xFFFFFFFFu, cj, k);
            uint2 hv = __ldg(&h2[(size_t)s * 32 + lane]);
            float2 f01 = __half22float2(*reinterpret_cast<__half2*>(&hv.x));
            float2 f23 = __half22float2(*reinterpret_cast<__half2*>(&hv.y));
            acc.x += c * f01.x;
            acc.y += c * f01.y;
            acc.z += c * f23.x;
            acc.w += c * f23.y;
        }
    }

    reinterpret_cast<float4*>(z)[(size_t)t * (DIM / 4) + lane] = acc;
}

// ---------------------------------------------------------------------------
// Launch. Inputs: h[N*D] f32, d[N] f32, w[E] f32, gate_w[2D] f32,
// gate_b[1] f32, src[E] i32, dst[E] i32. Output z[N*D] f32.
// ---------------------------------------------------------------------------
extern "C" void kernel_launch(void* const* d_in, const int* in_sizes, int n_in,
                              void* d_out, int out_size)
{
    const float* h      = (const float*)d_in[0];
    const float* d      = (const float*)d_in[1];
    const float* w      = (const float*)d_in[2];
    const float* gate_w = (const float*)d_in[3];
    const float* gate_b = (const float*)d_in[4];
    const int*   src    = (const int*)d_in[5];
    const int*   dst    = (const int*)d_in[6];
    float*       z      = (float*)d_out;

    const int n = in_sizes[1];      // N
    const int E = in_sizes[2];      // E
    const int ntiles = (n + SCAN_TILE - 1) / SCAN_TILE;

    // Zero degree counters via memset (graph-capturable, no alloc).
    void* counts_ptr = nullptr;
    cudaGetSymbolAddress(&counts_ptr, g_counts);
    cudaMemsetAsync(counts_ptr, 0, (size_t)n * sizeof(int));

    // 1. Gate scores + fp16 h conversion (one warp per node).
    node_scores_kernel<<<(n + 7) / 8, 256>>>(h, d, gate_w, gate_b, n);

    // 2. Degree histogram.
    hist_kernel<<<(E + 255) / 256, 256>>>(dst, E, n);

    // 3. Tiled exclusive scan + fused base apply / cursor init.
    scan_tile_kernel<<<ntiles, SCAN_TILE>>>(n);
    add_base_kernel<<<(n + 255) / 256, 256>>>(n, ntiles);

    // 4. Scatter edges into dst-sorted (src, coef) pairs.
    scatter_kernel<<<(E + 255) / 256, 256>>>(w, src, dst, E, n);

    // 5. Register-accumulated segment sum; writes every z row once.
    gather_kernel<<<(n + 7) / 8, 256>>>(z, n);
}